// round 8
// baseline (speedup 1.0000x reference)
#include <cuda_runtime.h>
#include <cuda_fp16.h>
#include <cstdint>

#define BB 64
#define TSTEPS 512
#define HH 512

// ---------------- static device scratch ----------------
__device__ __align__(16) __half g_xh[TSTEPS * BB * 256];        // x fp16, [T][B][256]
__device__ __align__(16) __half g_h0[(TSTEPS + 1) * BB * HH];   // layer0 h seq, slot0 = 0
__device__ __align__(16) __half g_h1[(TSTEPS + 1) * BB * HH];   // layer1 h seq, slot0 = 0
__device__ unsigned g_c0;                                       // monotonic arrival counters
__device__ unsigned g_c1;

// ---------------- PTX helpers ----------------
__device__ __forceinline__ void cp16(uint32_t dst, const void* src) {
    asm volatile("cp.async.cg.shared.global [%0], [%1], 16;\n" :: "r"(dst), "l"(src));
}
__device__ __forceinline__ void cp_commit() { asm volatile("cp.async.commit_group;\n"); }
template<int N> __device__ __forceinline__ void cp_wait() {
    asm volatile("cp.async.wait_group %0;\n" :: "n"(N));
}
__device__ __forceinline__ void ldsm4(uint32_t& r0, uint32_t& r1, uint32_t& r2, uint32_t& r3,
                                      uint32_t a) {
    asm volatile("ldmatrix.sync.aligned.m8n8.x4.shared.b16 {%0,%1,%2,%3}, [%4];\n"
                 : "=r"(r0), "=r"(r1), "=r"(r2), "=r"(r3) : "r"(a));
}
__device__ __forceinline__ void mma16816(float* c,
                                         uint32_t a0, uint32_t a1, uint32_t a2, uint32_t a3,
                                         uint32_t b0, uint32_t b1) {
    asm volatile("mma.sync.aligned.m16n8k16.row.col.f32.f16.f16.f32 "
                 "{%0,%1,%2,%3}, {%4,%5,%6,%7}, {%8,%9}, {%0,%1,%2,%3};\n"
                 : "+f"(c[0]), "+f"(c[1]), "+f"(c[2]), "+f"(c[3])
                 : "r"(a0), "r"(a1), "r"(a2), "r"(a3), "r"(b0), "r"(b1));
}
__device__ __forceinline__ unsigned ld_acq(const unsigned* p) {
    unsigned v;
    asm volatile("ld.acquire.gpu.global.u32 %0, [%1];" : "=r"(v) : "l"(p) : "memory");
    return v;
}
__device__ __forceinline__ void red_rel(unsigned* p) {
    asm volatile("red.release.gpu.global.add.u32 [%0], 1;" :: "l"(p) : "memory");
}
__device__ __forceinline__ void poll_ge(const unsigned* p, unsigned v) {
    if (ld_acq(p) >= v) return;
    while (ld_acq(p) < v) { __nanosleep(32); }
}

// ---------------- SMEM layout ----------------
// [0..64)        control (unused)
// [64..192)      bias (32 floats)
// [256..69888)   stash: 8 x [64 rows x 34 floats] fp32 partial gates
// [69888..200960) A chunk buffers: 8 x 16KB (64 rows x 128 halves, swizzled)
//                W slice overlaid here during init only (<=64KB)
#define BIAS_OFF 64
#define STASH_OFF 256
#define ASTART 69888
#define SMEM_SZ 200960

// ---------------- stage one 128-half K chunk: 64 rows, swizzled ----------------
__device__ __forceinline__ void stage_chunk(uint32_t cb, const __half* src, int sstride) {
    int tid = threadIdx.x;
#pragma unroll
    for (int i = 0; i < 2; i++) {
        int idx = tid + i * 512;
        int row = idx >> 4, u = idx & 15;
        cp16(cb + row * 256 + (((u) ^ (row & 7)) << 4), src + row * sstride + u * 8);
    }
}

// ---------------- prep kernels ----------------
__global__ void prep_x_k(const float* __restrict__ x) {
    int i = blockIdx.x * 256 + threadIdx.x;
    int f2 = i & 127;
    int t  = (i >> 7) & 511;
    int b  = i >> 16;
    float2 v = *(const float2*)(x + ((b * 512 + t) * 256 + f2 * 2));
    *((__half2*)(g_xh + (t * 64 + b) * 256 + f2 * 2)) = __floats2half2_rn(v.x, v.y);
}

__global__ void zero_k() {
    int i = blockIdx.x * 256 + threadIdx.x;
    __half2 z = __floats2half2_rn(0.f, 0.f);
    ((__half2*)g_h0)[i] = z;
    ((__half2*)g_h1)[i] = z;
    if (i == 0) { g_c0 = 0; g_c1 = 0; }
}

// ---------------- fused two-layer pipelined persistent kernel ----------------
// CTAs [0,64): layer 0.  CTAs [64,128): layer 1, one step behind.
// 512 threads = 16 warps: warp w -> k-chunk g = w>>1, m-half mh = w&1.
// W fragments for each warp's (32 cols x 128 k) slice hoisted to registers once.
template<int GRP>
__device__ __forceinline__ void run_group(char* dsm, int lx,
        const float* __restrict__ Wih, const float* __restrict__ Whh,
        const float* __restrict__ bih, const float* __restrict__ bhh,
        float* __restrict__ outp) {
    constexpr int KIN  = GRP ? 512 : 256;    // non-recurrent K
    constexpr int NRC  = KIN / 128;          // non-recurrent chunks
    constexpr int NCH  = NRC + 4;            // total chunks (R part = 4)
    constexpr int KTOT = NCH * 128;
    constexpr int ROWB = KTOT * 2;           // W smem row bytes (init overlay)
    constexpr int NRSTR = GRP ? HH : 256;    // NR source row stride

    const __half* nrs = GRP ? (g_h0 + (size_t)BB * HH) : g_xh;  // NR source (t=1 slice)
    __half* hbuf      = GRP ? g_h1 : g_h0;
    unsigned* own     = GRP ? &g_c1 : &g_c0;

    uint32_t smb = (uint32_t)__cvta_generic_to_shared(dsm);
    float* stash = (float*)(dsm + STASH_OFF);
    float* bsm   = (float*)(dsm + BIAS_OFF);
    int tid = threadIdx.x, lane = tid & 31, w = tid >> 5;
    int g = w >> 1, mh = w & 1;

    // ---- init: W slice into overlay smem (row n = gate*8+unit, KTOT halves, swizzled) ----
    for (int idx = tid; idx < 32 * (KTOT / 4); idx += 512) {
        int n  = idx / (KTOT / 4);
        int kk = (idx % (KTOT / 4)) * 4;
        int gr = (n >> 3) * HH + lx * 8 + (n & 7);
        float4 v = (kk < KIN) ? *(const float4*)(Wih + (size_t)gr * KIN + kk)
                              : *(const float4*)(Whh + (size_t)gr * HH + (kk - KIN));
        __half2 p0 = __floats2half2_rn(v.x, v.y);
        __half2 p1 = __floats2half2_rn(v.z, v.w);
        char* dst = dsm + ASTART + n * ROWB + (((kk >> 3) ^ (n & 7)) << 4) + (kk & 7) * 2;
        *(__half2*)dst       = p0;
        *(__half2*)(dst + 4) = p1;
    }
    if (tid < 32) {
        int gr = (tid >> 3) * HH + lx * 8 + (tid & 7);
        bsm[tid] = bih[gr] + bhh[gr];
    }
    __syncthreads();

    // ---- hoist this warp's W fragments: 32 cols x 128 k-halves = 64 regs ----
    uint32_t wr[64];
    if (g < NCH) {
#pragma unroll
        for (int cg = 0; cg < 4; cg++) {
            int rB = cg * 8 + (lane & 7);
            uint32_t base = smb + ASTART + rB * ROWB;
            int bsw = rB & 7;
#pragma unroll
            for (int q = 0; q < 4; q++) {
                int ku = g * 16 + q * 4 + (lane >> 3);
                ldsm4(wr[(cg * 4 + q) * 4 + 0], wr[(cg * 4 + q) * 4 + 1],
                      wr[(cg * 4 + q) * 4 + 2], wr[(cg * 4 + q) * 4 + 3],
                      base + ((ku ^ bsw) << 4));
            }
        }
    }
    __syncthreads();   // W overlay region now free -> A chunk buffers

    float cst[2] = {0.f, 0.f};

    for (int t = 1; t <= TSTEPS; t++) {
        // ---- poll own recurrence; grp0 stages x (dependency-free) first ----
        if (GRP == 0) {
#pragma unroll
            for (int c = 0; c < NRC; c++)
                stage_chunk(smb + ASTART + c * 16384,
                            nrs + (size_t)(t - 1) * BB * NRSTR + c * 128, NRSTR);
            cp_commit();
        }
        if (tid == 0) poll_ge(own, 64u * (t - 1));
        __syncthreads();
        // R chunks: own h[t-1]
#pragma unroll
        for (int c = 0; c < 4; c++)
            stage_chunk(smb + ASTART + (NRC + c) * 16384,
                        hbuf + (size_t)(t - 1) * BB * HH + c * 128, HH);
        cp_commit();
        if (GRP == 1) {       // NR chunks: h0[t] (usually already published)
            if (tid == 0) poll_ge(&g_c0, 64u * t);
            __syncthreads();
#pragma unroll
            for (int c = 0; c < NRC; c++)
                stage_chunk(smb + ASTART + c * 16384,
                            nrs + (size_t)(t - 1) * BB * NRSTR + c * 128, NRSTR);
            cp_commit();
        }
        cp_wait<0>();
        __syncthreads();

        // ---- gemm: warp (g, mh) computes its k-chunk partial for 32 rows ----
        if (g < NCH) {
            uint32_t ab0 = smb + ASTART + g * 16384;
            int akc = lane >> 4;
#pragma unroll
            for (int mt = 0; mt < 2; mt++) {
                float acc[16];
#pragma unroll
                for (int i = 0; i < 16; i++) acc[i] = 0.f;
                int rA = mh * 32 + mt * 16 + (lane & 15);
                uint32_t ab = ab0 + rA * 256;
                int asw = rA & 7;
#pragma unroll
                for (int ks = 0; ks < 8; ks++) {
                    uint32_t a0, a1, a2, a3;
                    ldsm4(a0, a1, a2, a3, ab + (((2 * ks + akc) ^ asw) << 4));
                    int q = ks >> 1, off = (ks & 1) * 2;
#pragma unroll
                    for (int nt = 0; nt < 4; nt++)
                        mma16816(acc + nt * 4, a0, a1, a2, a3,
                                 wr[(nt * 4 + q) * 4 + off], wr[(nt * 4 + q) * 4 + off + 1]);
                }
                int r0 = mh * 32 + mt * 16 + (lane >> 2);
                float* sp = stash + g * 2176 + r0 * 34 + (lane & 3) * 2;
#pragma unroll
                for (int nt = 0; nt < 4; nt++) {
                    *(float2*)(sp + nt * 8)          = make_float2(acc[nt * 4],     acc[nt * 4 + 1]);
                    *(float2*)(sp + 8 * 34 + nt * 8) = make_float2(acc[nt * 4 + 2], acc[nt * 4 + 3]);
                }
            }
        }
        __syncthreads();

        // ---- pointwise LSTM: threads 0..255, each (batch b, unit pair up) ----
        if (tid < 256) {
            int b = tid >> 2, up = tid & 3;
            __half hv[2];
            float ov[2];
#pragma unroll
            for (int e = 0; e < 2; e++) {
                int u = up * 2 + e;
                float zi = bsm[u], zf = bsm[8 + u], zg = bsm[16 + u], zo = bsm[24 + u];
                const float* sb = stash + b * 34 + u;
#pragma unroll
                for (int q = 0; q < NCH; q++) {
                    const float* p = sb + q * 2176;
                    zi += p[0]; zf += p[8]; zg += p[16]; zo += p[24];
                }
                float iv = 1.f / (1.f + __expf(-zi));
                float fv = 1.f / (1.f + __expf(-zf));
                float gv = tanhf(zg);
                float o  = 1.f / (1.f + __expf(-zo));
                cst[e] = fv * cst[e] + iv * gv;
                float hvf = o * tanhf(cst[e]);
                hv[e] = __float2half(hvf);
                ov[e] = hvf;
            }
            *(__half2*)(hbuf + (size_t)t * BB * HH + b * HH + lx * 8 + up * 2) =
                *(__half2*)hv;
            if (GRP == 1)
                *(float2*)(outp + ((size_t)b * TSTEPS + (t - 1)) * HH + lx * 8 + up * 2) =
                    make_float2(ov[0], ov[1]);
        }
        __syncthreads();
        if (tid == 0) red_rel(own);   // release: h[t] published
    }
}

__global__ void __launch_bounds__(512, 1) lstm_fused(
        const float* __restrict__ Wih0, const float* __restrict__ Whh0,
        const float* __restrict__ bih0, const float* __restrict__ bhh0,
        const float* __restrict__ Wih1, const float* __restrict__ Whh1,
        const float* __restrict__ bih1, const float* __restrict__ bhh1,
        float* __restrict__ outp) {
    extern __shared__ char dsm[];
    int bx = blockIdx.x;
    if (bx < 64) run_group<0>(dsm, bx,      Wih0, Whh0, bih0, bhh0, nullptr);
    else         run_group<1>(dsm, bx - 64, Wih1, Whh1, bih1, bhh1, outp);
}

// ---------------- host launcher ----------------
extern "C" void kernel_launch(void* const* d_in, const int* in_sizes, int n_in,
                              void* d_out, int out_size) {
    const float* x    = (const float*)d_in[0];
    const float* Wih0 = (const float*)d_in[1];
    const float* Whh0 = (const float*)d_in[2];
    const float* bih0 = (const float*)d_in[3];
    const float* bhh0 = (const float*)d_in[4];
    const float* Wih1 = (const float*)d_in[5];
    const float* Whh1 = (const float*)d_in[6];
    const float* bih1 = (const float*)d_in[7];
    const float* bhh1 = (const float*)d_in[8];
    float* out = (float*)d_out;

    cudaFuncSetAttribute(lstm_fused, cudaFuncAttributeMaxDynamicSharedMemorySize, SMEM_SZ);

    prep_x_k<<<16384, 256>>>(x);
    zero_k<<<64, 256>>>();
    lstm_fused<<<128, 512, SMEM_SZ>>>(Wih0, Whh0, bih0, bhh0,
                                      Wih1, Whh1, bih1, bhh1, out);
}

// round 9
// speedup vs baseline: 1.4780x; 1.4780x over previous
#include <cuda_runtime.h>
#include <cuda_fp16.h>
#include <cstdint>

#define BB 64
#define TSTEPS 512
#define HH 512

// ---------------- static device scratch ----------------
__device__ __align__(16) __half g_xh[TSTEPS * BB * 256];        // x fp16, [T][B][256]
__device__ __align__(16) __half g_h0[(TSTEPS + 1) * BB * HH];   // layer0 h seq, slot0 = 0
__device__ __align__(16) __half g_h1[(TSTEPS + 1) * BB * HH];   // layer1 h seq, slot0 = 0
__device__ unsigned g_c0;                                       // monotonic arrival counters
__device__ unsigned g_c1;

// ---------------- PTX helpers ----------------
__device__ __forceinline__ void cp16(uint32_t dst, const void* src) {
    asm volatile("cp.async.cg.shared.global [%0], [%1], 16;\n" :: "r"(dst), "l"(src));
}
__device__ __forceinline__ void cp_commit() { asm volatile("cp.async.commit_group;\n"); }
template<int N> __device__ __forceinline__ void cp_wait() {
    asm volatile("cp.async.wait_group %0;\n" :: "n"(N));
}
__device__ __forceinline__ void ldsm4(uint32_t& r0, uint32_t& r1, uint32_t& r2, uint32_t& r3,
                                      uint32_t a) {
    asm volatile("ldmatrix.sync.aligned.m8n8.x4.shared.b16 {%0,%1,%2,%3}, [%4];\n"
                 : "=r"(r0), "=r"(r1), "=r"(r2), "=r"(r3) : "r"(a));
}
__device__ __forceinline__ void mma16816(float* c,
                                         uint32_t a0, uint32_t a1, uint32_t a2, uint32_t a3,
                                         uint32_t b0, uint32_t b1) {
    asm volatile("mma.sync.aligned.m16n8k16.row.col.f32.f16.f16.f32 "
                 "{%0,%1,%2,%3}, {%4,%5,%6,%7}, {%8,%9}, {%0,%1,%2,%3};\n"
                 : "+f"(c[0]), "+f"(c[1]), "+f"(c[2]), "+f"(c[3])
                 : "r"(a0), "r"(a1), "r"(a2), "r"(a3), "r"(b0), "r"(b1));
}
__device__ __forceinline__ unsigned ld_acq(const unsigned* p) {
    unsigned v;
    asm volatile("ld.acquire.gpu.global.u32 %0, [%1];" : "=r"(v) : "l"(p) : "memory");
    return v;
}
__device__ __forceinline__ void red_rel(unsigned* p) {
    asm volatile("red.release.gpu.global.add.u32 [%0], 1;" :: "l"(p) : "memory");
}

// ---------------- A staging: 64 rows x UNITS 16B-units, swizzled (512 thr) ----------------
template<int UNITS>
__device__ __forceinline__ void stage(uint32_t dst, int arb, const __half* src,
                                      int sstride, int kcoff) {
    int tid = threadIdx.x;
#pragma unroll
    for (int i = 0; i < (64 * UNITS) / 512; i++) {
        int idx = tid + i * 512;
        int r = idx / UNITS, kc = idx % UNITS;
        cp16(dst + r * arb + (((kc + kcoff) ^ (r & 7)) << 4), src + r * sstride + kc * 8);
    }
}

// ---------------- GEMM: warp (kq=w>>2, m=w&3) computes 16 rows x 32 cols, K slice ----------------
// au0/wu0 are 16B-unit indices (already include the warp's k-quarter offset).
template<int NP>   // NP iterations of 4 units (64 halves) each
__device__ __forceinline__ void gemm4(float* acc, uint32_t asmb, int arb,
                                      uint32_t wsmb, int rowb, int au0, int wu0) {
    int tid = threadIdx.x, lane = tid & 31, w = tid >> 5;
    int m0 = (w & 3) * 16;
    int rA = m0 + (lane & 15);
    uint32_t abase = asmb + rA * arb;
    int asw = rA & 7, akc = lane >> 4;
    int bm = lane >> 3, bsw = lane & 7;
    uint32_t bb0 = wsmb + (lane & 7) * rowb;
#pragma unroll
    for (int p = 0; p < NP; p++) {
        int au = au0 + 4 * p, wu = wu0 + 4 * p;
        uint32_t a0, a1, a2, a3, a4, a5, a6, a7;
        ldsm4(a0, a1, a2, a3, abase + (((au + akc) ^ asw) << 4));
        ldsm4(a4, a5, a6, a7, abase + (((au + 2 + akc) ^ asw) << 4));
#pragma unroll
        for (int nt = 0; nt < 4; nt++) {
            uint32_t b0, b1, b2, b3;
            ldsm4(b0, b1, b2, b3, bb0 + nt * 8 * rowb + (((wu + bm) ^ bsw) << 4));
            mma16816(acc + nt * 4, a0, a1, a2, a3, b0, b1);
            mma16816(acc + nt * 4, a4, a5, a6, a7, b2, b3);
        }
    }
}

// ---------------- init kernel: x convert + h slot0 zero + counters ----------------
__global__ void init_k(const float* __restrict__ x) {
    int i = blockIdx.x * 256 + threadIdx.x;
    int f2 = i & 127;
    int t  = (i >> 7) & 511;
    int b  = i >> 16;
    float2 v = *(const float2*)(x + ((b * 512 + t) * 256 + f2 * 2));
    *((__half2*)(g_xh + (t * 64 + b) * 256 + f2 * 2)) = __floats2half2_rn(v.x, v.y);
    if (i < 16384) {
        __half2 z = __floats2half2_rn(0.f, 0.f);
        ((__half2*)g_h0)[i] = z;
        ((__half2*)g_h1)[i] = z;
    }
    if (i == 0) { g_c0 = 0; g_c1 = 0; }
}

// ---------------- fused two-layer pipelined persistent kernel ----------------
// CTAs [0,64): layer 0.  CTAs [64,128): layer 1, one step behind.
// 512 threads = 16 warps = 4(m) x 4(k-quarter); each warp covers all 32 gate cols.
template<int GRP>
__device__ __forceinline__ void run_group(char* dsm, int lx,
        const float* __restrict__ Wih, const float* __restrict__ Whh,
        const float* __restrict__ bih, const float* __restrict__ bhh,
        float* __restrict__ outp) {
    constexpr int KIN  = GRP ? 512 : 256;
    constexpr int KTOT = KIN + 512;
    constexpr int ROWB = KTOT * 2;                    // W smem row bytes
    constexpr int AOFF = GRP ? 65536 : 49152;         // h staging region (A)
    constexpr int ARB  = GRP ? 2048 : 1024;           // A row bytes
    constexpr int XOFF = 114688;                      // group0 x staging region
    constexpr int BOFF = GRP ? 196608 : 147456;       // bias
    // stash (4 x 64 rows x 40 floats) aliases the A region after gemm completes
    uint32_t smb = (uint32_t)__cvta_generic_to_shared(dsm);
    float* stash = (float*)(dsm + AOFF);
    float* bsm   = (float*)(dsm + BOFF);

    const __half* nrs = GRP ? (g_h0 + (size_t)BB * HH) : g_xh;   // NR source (t=1 slice)
    constexpr int NRSTR = GRP ? HH : 256;
    __half* hbuf  = GRP ? g_h1 : g_h0;
    unsigned* own = GRP ? &g_c1 : &g_c0;

    int tid = threadIdx.x, lane = tid & 31, w = tid >> 5;
    int m0 = (w & 3) * 16, kq = w >> 2;

    // ---- load & convert W slice: 32 rows ([Wih|Whh] along k), swizzled fp16, resident ----
    for (int idx = tid; idx < 32 * (KTOT / 4); idx += 512) {
        int n  = idx / (KTOT / 4);
        int kk = (idx % (KTOT / 4)) * 4;
        int gr = (n >> 3) * HH + lx * 8 + (n & 7);
        float4 v = (kk < KIN) ? *(const float4*)(Wih + (size_t)gr * KIN + kk)
                              : *(const float4*)(Whh + (size_t)gr * HH + (kk - KIN));
        __half2 p0 = __floats2half2_rn(v.x, v.y);
        __half2 p1 = __floats2half2_rn(v.z, v.w);
        char* dst = dsm + n * ROWB + (((kk >> 3) ^ (n & 7)) << 4) + (kk & 7) * 2;
        *(__half2*)dst       = p0;
        *(__half2*)(dst + 4) = p1;
    }
    if (tid < 32) {
        int gr = (tid >> 3) * HH + lx * 8 + (tid & 7);
        bsm[tid] = bih[gr] + bhh[gr];
    }
    __syncthreads();

    float cst = 0.f;                                  // c-state for (b=tid>>3, u=tid&7)
    float acc[16];
#pragma unroll
    for (int i = 0; i < 16; i++) acc[i] = 0.f;

    if (GRP == 0) {   // prologue: x contribution for step 1
        stage<32>(smb + XOFF, 512, g_xh, 256, 0);
        cp_commit(); cp_wait<0>(); __syncthreads();
        gemm4<2>(acc, smb + XOFF, 512, smb, ROWB, kq * 8, kq * 8);
    }

    for (int t = 1; t <= TSTEPS; t++) {
        if (GRP == 0) {
            if (tid == 0) { while (ld_acq(&g_c0) < 64u * (t - 1)) {} }
            __syncthreads();
            stage<64>(smb + AOFF, ARB, g_h0 + (size_t)(t - 1) * BB * HH, 512, 0);
            cp_commit(); cp_wait<0>(); __syncthreads();
            gemm4<4>(acc, smb + AOFF, ARB, smb, ROWB, kq * 16, 32 + kq * 16);
        } else {
            // h0[t] input part: group0 runs ahead, so this poll is usually instant
            if (tid == 0) { while (ld_acq(&g_c0) < 64u * t) {} }
            __syncthreads();
            stage<64>(smb + AOFF, ARB, g_h0 + (size_t)t * BB * HH, 512, 0);
            cp_commit();
            if (tid == 0) { while (ld_acq(&g_c1) < 64u * (t - 1)) {} }
            __syncthreads();
            stage<64>(smb + AOFF, ARB, g_h1 + (size_t)(t - 1) * BB * HH, 512, 64);
            cp_commit();
            cp_wait<1>(); __syncthreads();
            gemm4<4>(acc, smb + AOFF, ARB, smb, ROWB, kq * 16, kq * 16);          // h0
            cp_wait<0>(); __syncthreads();
            gemm4<4>(acc, smb + AOFF, ARB, smb, ROWB, 64 + kq * 16, 64 + kq * 16); // h1
        }

        // ---- all A reads done -> safe to alias stash into A region ----
        __syncthreads();
        {
            float* sp = stash + kq * 2560;
            int r0 = m0 + (lane >> 2), cb = 2 * (lane & 3);
#pragma unroll
            for (int nt = 0; nt < 4; nt++) {
                *(float2*)(sp + r0 * 40 + nt * 8 + cb)       =
                    make_float2(acc[nt * 4],     acc[nt * 4 + 1]);
                *(float2*)(sp + (r0 + 8) * 40 + nt * 8 + cb) =
                    make_float2(acc[nt * 4 + 2], acc[nt * 4 + 3]);
            }
        }
        __syncthreads();

        // ---- pointwise LSTM: thread owns (b = tid>>3, u = tid&7) ----
        {
            int b = tid >> 3, u = tid & 7;
            float zi = bsm[u], zf = bsm[8 + u], zg = bsm[16 + u], zo = bsm[24 + u];
#pragma unroll
            for (int q = 0; q < 4; q++) {
                const float* p = stash + q * 2560 + b * 40 + u;
                zi += p[0]; zf += p[8]; zg += p[16]; zo += p[24];
            }
            float iv = 1.f / (1.f + __expf(-zi));
            float fv = 1.f / (1.f + __expf(-zf));
            float gv = tanhf(zg);
            float ov = 1.f / (1.f + __expf(-zo));
            cst = fv * cst + iv * gv;
            float hvf = ov * tanhf(cst);
            hbuf[(size_t)t * BB * HH + b * HH + lx * 8 + u] = __float2half(hvf);
            if (GRP == 1)
                outp[((size_t)b * TSTEPS + (t - 1)) * HH + lx * 8 + u] = hvf;
        }
        __syncthreads();
        if (tid == 0) red_rel(own);   // release: h[t] published

#pragma unroll
        for (int i = 0; i < 16; i++) acc[i] = 0.f;

        if (GRP == 0 && t < TSTEPS) {   // x(t+1) GEMM in the publish shadow
            stage<32>(smb + XOFF, 512, g_xh + (size_t)t * BB * 256, 256, 0);
            cp_commit(); cp_wait<0>(); __syncthreads();
            gemm4<2>(acc, smb + XOFF, 512, smb, ROWB, kq * 8, kq * 8);
        }
    }
}

__global__ void __launch_bounds__(512, 1) lstm_fused(
        const float* __restrict__ Wih0, const float* __restrict__ Whh0,
        const float* __restrict__ bih0, const float* __restrict__ bhh0,
        const float* __restrict__ Wih1, const float* __restrict__ Whh1,
        const float* __restrict__ bih1, const float* __restrict__ bhh1,
        float* __restrict__ outp) {
    extern __shared__ char dsm[];
    int bx = blockIdx.x;
    if (bx < 64) run_group<0>(dsm, bx,      Wih0, Whh0, bih0, bhh0, nullptr);
    else         run_group<1>(dsm, bx - 64, Wih1, Whh1, bih1, bhh1, outp);
}

// ---------------- host launcher ----------------
extern "C" void kernel_launch(void* const* d_in, const int* in_sizes, int n_in,
                              void* d_out, int out_size) {
    const float* x    = (const float*)d_in[0];
    const float* Wih0 = (const float*)d_in[1];
    const float* Whh0 = (const float*)d_in[2];
    const float* bih0 = (const float*)d_in[3];
    const float* bhh0 = (const float*)d_in[4];
    const float* Wih1 = (const float*)d_in[5];
    const float* Whh1 = (const float*)d_in[6];
    const float* bih1 = (const float*)d_in[7];
    const float* bhh1 = (const float*)d_in[8];
    float* out = (float*)d_out;

    cudaFuncSetAttribute(lstm_fused, cudaFuncAttributeMaxDynamicSharedMemorySize, 197120);

    init_k<<<16384, 256>>>(x);
    lstm_fused<<<128, 512, 197120>>>(Wih0, Whh0, bih0, bhh0,
                                     Wih1, Whh1, bih1, bhh1, out);
}